// round 5
// baseline (speedup 1.0000x reference)
#include <cuda_runtime.h>

#define DD     262144     // 512*512
#define NB     128        // batch
#define NENV   4
#define KSEL   26214      // floor(0.1 * 512 * 512)
#define NBIN   65536

// Scratch (allocation-free: __device__ globals, zero-initialized at module load)
__device__ float    g_M[NENV][DD];        // per-env logits (4 MB, L2-resident)
__device__ unsigned g_hist[NENV][NBIN];   // radix pass 1 (hi 16 bits)
__device__ unsigned g_hist2[NENV][NBIN];  // radix pass 2 (lo 16 bits)
__device__ unsigned g_binhi[NENV];
__device__ unsigned g_rank[NENV];
__device__ unsigned g_kth[NENV];          // exact key of k-th largest per env

// Monotone mapping: float total order -> unsigned total order
__device__ __forceinline__ unsigned fkey(float f) {
    unsigned u = __float_as_uint(f);
    return (u & 0x80000000u) ? ~u : (u | 0x80000000u);
}
__device__ __forceinline__ float sigm(float x) {
    return __fdividef(1.0f, 1.0f + __expf(-x));   // MUFU EX2 + fast RCP
}

// Build per-env logits + hi-16 histogram. Flat grid (high occupancy).
// Requires g_hist == 0 on entry (guaranteed: zero-init at load, re-zeroed by k_scan(1)).
__global__ void k_build(const float* __restrict__ base, const float* __restrict__ deltas) {
    int e = blockIdx.y;
    int i = (blockIdx.x * 256 + threadIdx.x) * 4;
    float4 b4 = *(const float4*)(base + i);
    float4 d4 = *(const float4*)(deltas + (size_t)e * DD + i);
    float4 m;
    m.x = b4.x + d4.x; m.y = b4.y + d4.y;
    m.z = b4.z + d4.z; m.w = b4.w + d4.w;
    *(float4*)(&g_M[e][i]) = m;
    atomicAdd(&g_hist[e][fkey(m.x) >> 16], 1u);
    atomicAdd(&g_hist[e][fkey(m.y) >> 16], 1u);
    atomicAdd(&g_hist[e][fkey(m.z) >> 16], 1u);
    atomicAdd(&g_hist[e][fkey(m.w) >> 16], 1u);
}

// Rank-select over a 65536-bin histogram (descending), parallel suffix-scan.
// phase 0: g_hist  -> (binhi, remaining rank); also zeroes g_hist2 for pass 2.
// phase 1: g_hist2 -> exact kth key; also re-zeroes g_hist for the next call.
__global__ void k_scan(int phase) {
    int e = blockIdx.x;
    int t = threadIdx.x;
    const unsigned* h = (phase == 0) ? &g_hist[e][0] : &g_hist2[e][0];
    __shared__ unsigned ss[1024];

    unsigned s = 0;
    #pragma unroll 4
    for (int j = 0; j < 64; j++) {
        s += h[t * 64 + j];
        if (phase == 0) g_hist2[e][t * 64 + j] = 0u;   // prep pass 2
        else            g_hist[e][t * 64 + j]  = 0u;   // clean for next graph replay
    }
    ss[t] = s;
    __syncthreads();
    // inclusive suffix sum: ss[t] = sum_{j>=t} chunk[j]
    for (int off = 1; off < 1024; off <<= 1) {
        unsigned v = (t + off < 1024) ? ss[t + off] : 0u;
        __syncthreads();
        ss[t] += v;
        __syncthreads();
    }
    unsigned target = (phase == 0) ? (unsigned)KSEL : g_rank[e];
    unsigned above = (t < 1023) ? ss[t + 1] : 0u;
    if (ss[t] >= target && above < target) {
        unsigned cum = above;
        unsigned bin = (unsigned)(t * 64);
        for (int j = 63; j >= 0; j--) {
            unsigned v = h[t * 64 + j];
            if (cum + v >= target) { bin = (unsigned)(t * 64 + j); break; }
            cum += v;
        }
        if (phase == 0) {
            g_binhi[e] = bin;
            g_rank[e]  = target - cum;
        } else {
            g_kth[e] = (g_binhi[e] << 16) | bin;
        }
    }
}

// Lo-16 histogram restricted to the selected hi-bin. Flat grid.
__global__ void k_hist2() {
    int e = blockIdx.y;
    unsigned hi = g_binhi[e];
    int i = (blockIdx.x * 256 + threadIdx.x) * 4;
    float4 m = *(const float4*)(&g_M[e][i]);
    unsigned k0 = fkey(m.x), k1 = fkey(m.y), k2 = fkey(m.z), k3 = fkey(m.w);
    if ((k0 >> 16) == hi) atomicAdd(&g_hist2[e][k0 & 0xFFFFu], 1u);
    if ((k1 >> 16) == hi) atomicAdd(&g_hist2[e][k1 & 0xFFFFu], 1u);
    if ((k2 >> 16) == hi) atomicAdd(&g_hist2[e][k2 & 0xFFFFu], 1u);
    if ((k3 >> 16) == hi) atomicAdd(&g_hist2[e][k3 & 0xFFFFu], 1u);
}

// Flat streaming writer: per (column-chunk, batch-row) block; single L2 read of
// g_M, sigmoid recomputed via MUFU, 3 dense coalesced float4 streams, PLAIN
// stores (L2 write-back aggregation; __stcs measured ~25-30us slower in R3/R4).
__global__ void k_out(const int* __restrict__ env_idx,
                      float* __restrict__ outA,
                      float* __restrict__ outL,
                      float* __restrict__ outS) {
    int b = blockIdx.y;
    int e = __ldg(&env_idx[b]);
    unsigned kth = g_kth[e];
    size_t i = ((size_t)blockIdx.x * 256 + threadIdx.x) * 4;
    float4 m = *(const float4*)(&g_M[e][i]);
    float4 s;
    s.x = sigm(m.x); s.y = sigm(m.y); s.z = sigm(m.z); s.w = sigm(m.w);
    float4 a;
    a.x = (fkey(m.x) >= kth) ? s.x : 0.0f;
    a.y = (fkey(m.y) >= kth) ? s.y : 0.0f;
    a.z = (fkey(m.z) >= kth) ? s.z : 0.0f;
    a.w = (fkey(m.w) >= kth) ? s.w : 0.0f;
    size_t off = (size_t)b * DD + i;
    *(float4*)(outA + off) = a;
    *(float4*)(outL + off) = m;
    *(float4*)(outS + off) = s;
}

extern "C" void kernel_launch(void* const* d_in, const int* in_sizes, int n_in,
                              void* d_out, int out_size) {
    const float* base   = nullptr;
    const float* deltas = nullptr;
    const int*   env    = nullptr;
    for (int i = 0; i < n_in; i++) {
        if      (in_sizes[i] == DD)        base   = (const float*)d_in[i];
        else if (in_sizes[i] == NENV * DD) deltas = (const float*)d_in[i];
        else if (in_sizes[i] == NB)        env    = (const int*)d_in[i];
        // z_s (131072 elems) unused by the reference outputs
    }

    dim3 gb(DD / 1024, NENV);               // (256, 4): 1 float4/thread
    k_build<<<gb, 256>>>(base, deltas);
    k_scan<<<NENV, 1024>>>(0);
    k_hist2<<<gb, 256>>>();
    k_scan<<<NENV, 1024>>>(1);

    float* outA = (float*)d_out;            // tuple order: (A, A_logits, A_soft)
    float* outL = outA + (size_t)NB * DD;
    float* outS = outL + (size_t)NB * DD;
    dim3 go(DD / 1024, NB);                 // (256, 128): 1 float4/thread
    k_out<<<go, 256>>>(env, outA, outL, outS);
}

// round 6
// speedup vs baseline: 1.9773x; 1.9773x over previous
#include <cuda_runtime.h>

#define DD     262144     // 512*512
#define NB     128        // batch
#define NENV   4
#define KSEL   26214      // floor(0.1 * 512 * 512)
#define NBIN   65536

// Scratch (allocation-free: __device__ globals, zero-initialized at module load)
__device__ float    g_M[NENV][DD];        // per-env logits (4 MB, L2-resident)
__device__ unsigned g_hist[NENV][NBIN];   // radix pass 1 (hi 16 bits)
__device__ unsigned g_hist2[NENV][NBIN];  // radix pass 2 (lo 16 bits)
__device__ unsigned g_binhi[NENV];
__device__ unsigned g_rank[NENV];
__device__ unsigned g_kth[NENV];          // exact key of k-th largest per env

// Monotone mapping: float total order -> unsigned total order
__device__ __forceinline__ unsigned fkey(float f) {
    unsigned u = __float_as_uint(f);
    return (u & 0x80000000u) ? ~u : (u | 0x80000000u);
}
__device__ __forceinline__ float sigm(float x) {
    return __fdividef(1.0f, 1.0f + __expf(-x));   // MUFU EX2 + fast RCP
}

// Build per-env logits + hi-16 histogram. Flat grid (high occupancy).
// Requires g_hist == 0 on entry (zero-init at load, re-zeroed by k_scan(1)).
__global__ void k_build(const float* __restrict__ base, const float* __restrict__ deltas) {
    int e = blockIdx.y;
    int i = (blockIdx.x * 256 + threadIdx.x) * 4;
    float4 b4 = *(const float4*)(base + i);
    float4 d4 = *(const float4*)(deltas + (size_t)e * DD + i);
    float4 m;
    m.x = b4.x + d4.x; m.y = b4.y + d4.y;
    m.z = b4.z + d4.z; m.w = b4.w + d4.w;
    *(float4*)(&g_M[e][i]) = m;
    atomicAdd(&g_hist[e][fkey(m.x) >> 16], 1u);
    atomicAdd(&g_hist[e][fkey(m.y) >> 16], 1u);
    atomicAdd(&g_hist[e][fkey(m.z) >> 16], 1u);
    atomicAdd(&g_hist[e][fkey(m.w) >> 16], 1u);
}

// Rank-select over 65536 bins (descending), fully COALESCED loads/stores.
// Warp w owns bins [w*2048, (w+1)*2048); chunk = 64 bins summed by 2 coalesced
// warp loads + shuffle reduction. Zeroing of the other histogram is coalesced.
// phase 0: g_hist  -> (binhi, remaining rank); zeroes g_hist2.
// phase 1: g_hist2 -> exact kth key; re-zeroes g_hist for next graph replay.
__global__ void k_scan(int phase) {
    int e = blockIdx.x;
    int t = threadIdx.x;
    int lane = t & 31, w = t >> 5;
    const unsigned* h  = (phase == 0) ? &g_hist[e][0]  : &g_hist2[e][0];
    unsigned*       zh = (phase == 0) ? &g_hist2[e][0] : &g_hist[e][0];
    __shared__ unsigned ss[1024];
    __shared__ unsigned sel[2];       // [chunk id, cum above chunk]
    __shared__ unsigned bins64[64];

    // coalesced zero of the other histogram (consecutive threads, consecutive words)
    #pragma unroll 8
    for (int j = 0; j < 64; j++) zh[j * 1024 + t] = 0u;

    // chunk sums via coalesced loads + warp reduce
    const unsigned* hw = h + w * 2048;
    #pragma unroll 4
    for (int c = 0; c < 32; c++) {
        unsigned v = hw[c * 64 + lane] + hw[c * 64 + 32 + lane];
        #pragma unroll
        for (int o = 16; o > 0; o >>= 1) v += __shfl_down_sync(0xFFFFFFFFu, v, o);
        if (lane == 0) ss[w * 32 + c] = v;
    }
    __syncthreads();

    // inclusive suffix sum over the 1024 chunk sums: ss[t] = sum_{j>=t}
    for (int off = 1; off < 1024; off <<= 1) {
        unsigned v = (t + off < 1024) ? ss[t + off] : 0u;
        __syncthreads();
        ss[t] += v;
        __syncthreads();
    }

    unsigned target = (phase == 0) ? (unsigned)KSEL : g_rank[e];
    unsigned above = (t < 1023) ? ss[t + 1] : 0u;
    if (ss[t] >= target && above < target) { sel[0] = (unsigned)t; sel[1] = above; }
    __syncthreads();

    unsigned cstar = sel[0], cum0 = sel[1];
    if (w == 0) {                               // coalesced fetch of winning chunk
        bins64[lane]      = h[cstar * 64 + lane];
        bins64[lane + 32] = h[cstar * 64 + 32 + lane];
    }
    __syncthreads();

    if (t == 0) {
        unsigned cum = cum0;
        unsigned bin = cstar * 64;
        for (int j = 63; j >= 0; j--) {         // walk 64 bins in shared (cheap)
            unsigned v = bins64[j];
            if (cum + v >= target) { bin = cstar * 64 + j; break; }
            cum += v;
        }
        if (phase == 0) { g_binhi[e] = bin; g_rank[e] = target - cum; }
        else            { g_kth[e]  = (g_binhi[e] << 16) | bin; }
    }
}

// Lo-16 histogram restricted to the selected hi-bin. Flat grid.
__global__ void k_hist2() {
    int e = blockIdx.y;
    unsigned hi = g_binhi[e];
    int i = (blockIdx.x * 256 + threadIdx.x) * 4;
    float4 m = *(const float4*)(&g_M[e][i]);
    unsigned k0 = fkey(m.x), k1 = fkey(m.y), k2 = fkey(m.z), k3 = fkey(m.w);
    if ((k0 >> 16) == hi) atomicAdd(&g_hist2[e][k0 & 0xFFFFu], 1u);
    if ((k1 >> 16) == hi) atomicAdd(&g_hist2[e][k1 & 0xFFFFu], 1u);
    if ((k2 >> 16) == hi) atomicAdd(&g_hist2[e][k2 & 0xFFFFu], 1u);
    if ((k3 >> 16) == hi) atomicAdd(&g_hist2[e][k3 & 0xFFFFu], 1u);
}

// Flat streaming writer: single L2 read of g_M per element, MUFU sigmoid,
// 3 dense coalesced float4 streams, PLAIN stores (L2 write-back aggregation).
__global__ void k_out(const int* __restrict__ env_idx,
                      float* __restrict__ outA,
                      float* __restrict__ outL,
                      float* __restrict__ outS) {
    int b = blockIdx.y;
    int e = __ldg(&env_idx[b]);
    unsigned kth = g_kth[e];
    size_t i = ((size_t)blockIdx.x * 256 + threadIdx.x) * 4;
    float4 m = *(const float4*)(&g_M[e][i]);
    float4 s;
    s.x = sigm(m.x); s.y = sigm(m.y); s.z = sigm(m.z); s.w = sigm(m.w);
    float4 a;
    a.x = (fkey(m.x) >= kth) ? s.x : 0.0f;
    a.y = (fkey(m.y) >= kth) ? s.y : 0.0f;
    a.z = (fkey(m.z) >= kth) ? s.z : 0.0f;
    a.w = (fkey(m.w) >= kth) ? s.w : 0.0f;
    size_t off = (size_t)b * DD + i;
    *(float4*)(outA + off) = a;
    *(float4*)(outL + off) = m;
    *(float4*)(outS + off) = s;
}

extern "C" void kernel_launch(void* const* d_in, const int* in_sizes, int n_in,
                              void* d_out, int out_size) {
    const float* base   = nullptr;
    const float* deltas = nullptr;
    const int*   env    = nullptr;
    for (int i = 0; i < n_in; i++) {
        if      (in_sizes[i] == DD)        base   = (const float*)d_in[i];
        else if (in_sizes[i] == NENV * DD) deltas = (const float*)d_in[i];
        else if (in_sizes[i] == NB)        env    = (const int*)d_in[i];
        // z_s (131072 elems) unused by the reference outputs
    }

    dim3 gb(DD / 1024, NENV);               // (256, 4): 1 float4/thread
    k_build<<<gb, 256>>>(base, deltas);
    k_scan<<<NENV, 1024>>>(0);
    k_hist2<<<gb, 256>>>();
    k_scan<<<NENV, 1024>>>(1);

    float* outA = (float*)d_out;            // tuple order: (A, A_logits, A_soft)
    float* outL = outA + (size_t)NB * DD;
    float* outS = outL + (size_t)NB * DD;
    dim3 go(DD / 1024, NB);                 // (256, 128): 1 float4/thread
    k_out<<<go, 256>>>(env, outA, outL, outS);
}

// round 7
// speedup vs baseline: 2.1043x; 1.0642x over previous
#include <cuda_runtime.h>

#define DD     262144     // 512*512
#define NB     128        // batch
#define NENV   4
#define KSEL   26214      // floor(0.1 * 512 * 512)
#define NBIN   65536

// Scratch (allocation-free: __device__ globals, zero-initialized at module load)
__device__ float    g_M[NENV][DD];        // per-env logits (4 MB, L2-resident)
__device__ unsigned g_hist[NENV][NBIN];   // radix pass 1 (hi 16 bits)
__device__ unsigned g_hist2[NENV][NBIN];  // radix pass 2 (lo 16 bits)
__device__ unsigned g_binhi[NENV];
__device__ unsigned g_rank[NENV];
__device__ unsigned g_kth[NENV];          // exact key of k-th largest per env

// Monotone mapping: float total order -> unsigned total order
__device__ __forceinline__ unsigned fkey(float f) {
    unsigned u = __float_as_uint(f);
    return (u & 0x80000000u) ? ~u : (u | 0x80000000u);
}
__device__ __forceinline__ float sigm(float x) {
    return __fdividef(1.0f, 1.0f + __expf(-x));   // MUFU EX2 + fast RCP
}

// Build per-env logits + hi-16 histogram. Flat grid (high occupancy).
// Also zeroes g_hist2 (grid has exactly NENV*NBIN = 262144 threads: 1 word each),
// so it is ready for k_hist2's atomics later this same call.
// Requires g_hist == 0 on entry (load-time zero-init; re-zeroed by k_hist2).
__global__ void k_build(const float* __restrict__ base, const float* __restrict__ deltas) {
    int e = blockIdx.y;
    int tid = blockIdx.x * 256 + threadIdx.x;          // 0..65535 per env slice
    (&g_hist2[0][0])[e * NBIN + tid] = 0u;             // coalesced free zeroing
    int i = tid * 4;
    float4 b4 = *(const float4*)(base + i);
    float4 d4 = *(const float4*)(deltas + (size_t)e * DD + i);
    float4 m;
    m.x = b4.x + d4.x; m.y = b4.y + d4.y;
    m.z = b4.z + d4.z; m.w = b4.w + d4.w;
    *(float4*)(&g_M[e][i]) = m;
    atomicAdd(&g_hist[e][fkey(m.x) >> 16], 1u);
    atomicAdd(&g_hist[e][fkey(m.y) >> 16], 1u);
    atomicAdd(&g_hist[e][fkey(m.z) >> 16], 1u);
    atomicAdd(&g_hist[e][fkey(m.w) >> 16], 1u);
}

// Rank-select over 65536 bins (descending), fully coalesced. No zeroing here.
// phase 0: g_hist  -> (binhi, remaining rank)
// phase 1: g_hist2 -> exact kth key
__global__ void k_scan(int phase) {
    int e = blockIdx.x;
    int t = threadIdx.x;
    int lane = t & 31, w = t >> 5;
    const unsigned* h = (phase == 0) ? &g_hist[e][0] : &g_hist2[e][0];
    __shared__ unsigned ss[1024];
    __shared__ unsigned sel[2];       // [chunk id, cum above chunk]
    __shared__ unsigned bins64[64];

    // chunk sums: warp w owns bins [w*2048, (w+1)*2048), 2 coalesced loads/chunk
    const unsigned* hw = h + w * 2048;
    #pragma unroll 4
    for (int c = 0; c < 32; c++) {
        unsigned v = hw[c * 64 + lane] + hw[c * 64 + 32 + lane];
        #pragma unroll
        for (int o = 16; o > 0; o >>= 1) v += __shfl_down_sync(0xFFFFFFFFu, v, o);
        if (lane == 0) ss[w * 32 + c] = v;
    }
    __syncthreads();

    // inclusive suffix sum over 1024 chunk sums: ss[t] = sum_{j>=t}
    for (int off = 1; off < 1024; off <<= 1) {
        unsigned v = (t + off < 1024) ? ss[t + off] : 0u;
        __syncthreads();
        ss[t] += v;
        __syncthreads();
    }

    unsigned target = (phase == 0) ? (unsigned)KSEL : g_rank[e];
    unsigned above = (t < 1023) ? ss[t + 1] : 0u;
    if (ss[t] >= target && above < target) { sel[0] = (unsigned)t; sel[1] = above; }
    __syncthreads();

    unsigned cstar = sel[0], cum0 = sel[1];
    if (w == 0) {                               // coalesced fetch of winning chunk
        bins64[lane]      = h[cstar * 64 + lane];
        bins64[lane + 32] = h[cstar * 64 + 32 + lane];
    }
    __syncthreads();

    if (t == 0) {
        unsigned cum = cum0;
        unsigned bin = cstar * 64;
        for (int j = 63; j >= 0; j--) {         // walk 64 bins in shared (cheap)
            unsigned v = bins64[j];
            if (cum + v >= target) { bin = cstar * 64 + j; break; }
            cum += v;
        }
        if (phase == 0) { g_binhi[e] = bin; g_rank[e] = target - cum; }
        else            { g_kth[e]  = (g_binhi[e] << 16) | bin; }
    }
}

// Lo-16 histogram restricted to the selected hi-bin. Flat grid.
// Also re-zeroes g_hist (1 word/thread) so the next graph replay starts clean.
__global__ void k_hist2() {
    int e = blockIdx.y;
    unsigned hi = g_binhi[e];
    int tid = blockIdx.x * 256 + threadIdx.x;
    (&g_hist[0][0])[e * NBIN + tid] = 0u;              // coalesced free zeroing
    int i = tid * 4;
    float4 m = *(const float4*)(&g_M[e][i]);
    unsigned k0 = fkey(m.x), k1 = fkey(m.y), k2 = fkey(m.z), k3 = fkey(m.w);
    if ((k0 >> 16) == hi) atomicAdd(&g_hist2[e][k0 & 0xFFFFu], 1u);
    if ((k1 >> 16) == hi) atomicAdd(&g_hist2[e][k1 & 0xFFFFu], 1u);
    if ((k2 >> 16) == hi) atomicAdd(&g_hist2[e][k2 & 0xFFFFu], 1u);
    if ((k3 >> 16) == hi) atomicAdd(&g_hist2[e][k3 & 0xFFFFu], 1u);
}

// Flat streaming writer: single L2 read of g_M per element, MUFU sigmoid,
// 3 dense coalesced float4 streams, PLAIN stores (L2 write-back aggregation).
__global__ void k_out(const int* __restrict__ env_idx,
                      float* __restrict__ outA,
                      float* __restrict__ outL,
                      float* __restrict__ outS) {
    int b = blockIdx.y;
    int e = __ldg(&env_idx[b]);
    unsigned kth = g_kth[e];
    size_t i = ((size_t)blockIdx.x * 256 + threadIdx.x) * 4;
    float4 m = *(const float4*)(&g_M[e][i]);
    float4 s;
    s.x = sigm(m.x); s.y = sigm(m.y); s.z = sigm(m.z); s.w = sigm(m.w);
    float4 a;
    a.x = (fkey(m.x) >= kth) ? s.x : 0.0f;
    a.y = (fkey(m.y) >= kth) ? s.y : 0.0f;
    a.z = (fkey(m.z) >= kth) ? s.z : 0.0f;
    a.w = (fkey(m.w) >= kth) ? s.w : 0.0f;
    size_t off = (size_t)b * DD + i;
    *(float4*)(outA + off) = a;
    *(float4*)(outL + off) = m;
    *(float4*)(outS + off) = s;
}

extern "C" void kernel_launch(void* const* d_in, const int* in_sizes, int n_in,
                              void* d_out, int out_size) {
    const float* base   = nullptr;
    const float* deltas = nullptr;
    const int*   env    = nullptr;
    for (int i = 0; i < n_in; i++) {
        if      (in_sizes[i] == DD)        base   = (const float*)d_in[i];
        else if (in_sizes[i] == NENV * DD) deltas = (const float*)d_in[i];
        else if (in_sizes[i] == NB)        env    = (const int*)d_in[i];
        // z_s (131072 elems) unused by the reference outputs
    }

    dim3 gb(DD / 1024, NENV);               // (256, 4): 1 float4/thread
    k_build<<<gb, 256>>>(base, deltas);
    k_scan<<<NENV, 1024>>>(0);
    k_hist2<<<gb, 256>>>();
    k_scan<<<NENV, 1024>>>(1);

    float* outA = (float*)d_out;            // tuple order: (A, A_logits, A_soft)
    float* outL = outA + (size_t)NB * DD;
    float* outS = outL + (size_t)NB * DD;
    dim3 go(DD / 1024, NB);                 // (256, 128): 1 float4/thread
    k_out<<<go, 256>>>(env, outA, outL, outS);
}

// round 9
// speedup vs baseline: 2.2869x; 1.0868x over previous
#include <cuda_runtime.h>

#define DD     262144     // 512*512
#define NB     128        // batch
#define NENV   4
#define KSEL   26214      // floor(0.1 * 512 * 512)
#define NBIN   65536
#define NCRS   1024       // coarse bins = fkey >> 22

// Scratch (allocation-free: __device__ globals, zero-initialized at module load)
__device__ float    g_M[NENV][DD];         // per-env logits (4 MB, L2-resident)
__device__ unsigned g_hist[NENV][NBIN];    // fine pass 1 (hi 16 bits)
__device__ unsigned g_hist2[NENV][NBIN];   // fine pass 2 (lo 16 bits)
__device__ unsigned g_coarse[NENV][NCRS];  // chunk sums of g_hist  (fkey>>22)
__device__ unsigned g_coarse2[NENV][NCRS]; // chunk sums of g_hist2 (lo>>6)
__device__ unsigned g_binhi[NENV];
__device__ unsigned g_rank[NENV];
__device__ unsigned g_kth[NENV];           // exact key of k-th largest per env

// Monotone mapping: float total order -> unsigned total order
__device__ __forceinline__ unsigned fkey(float f) {
    unsigned u = __float_as_uint(f);
    return (u & 0x80000000u) ? ~u : (u | 0x80000000u);
}
__device__ __forceinline__ float sigm(float x) {
    return __fdividef(1.0f, 1.0f + __expf(-x));   // MUFU EX2 + fast RCP
}

// Build per-env logits + hi-16 fine histogram + coarse chunk sums (smem-agg).
// Also zeroes g_hist2 (1 word/thread) and g_coarse2 for this call's pass 2.
// Requires g_hist/g_coarse == 0 on entry (load-time zero; re-zeroed by k_hist2).
__global__ void k_build(const float* __restrict__ base, const float* __restrict__ deltas) {
    __shared__ unsigned sc[NCRS];
    int e = blockIdx.y;
    int t = threadIdx.x;                                // 0..255
    int tid = blockIdx.x * 256 + t;                     // 0..65535 per env slice
    sc[t] = 0u; sc[t + 256] = 0u; sc[t + 512] = 0u; sc[t + 768] = 0u;
    (&g_hist2[0][0])[e * NBIN + tid] = 0u;              // coalesced free zeroing
    if (tid < NCRS) g_coarse2[e][tid] = 0u;
    __syncthreads();

    int i = tid * 4;
    float4 b4 = *(const float4*)(base + i);
    float4 d4 = *(const float4*)(deltas + (size_t)e * DD + i);
    float4 m;
    m.x = b4.x + d4.x; m.y = b4.y + d4.y;
    m.z = b4.z + d4.z; m.w = b4.w + d4.w;
    *(float4*)(&g_M[e][i]) = m;
    unsigned k0 = fkey(m.x), k1 = fkey(m.y), k2 = fkey(m.z), k3 = fkey(m.w);
    atomicAdd(&g_hist[e][k0 >> 16], 1u);
    atomicAdd(&g_hist[e][k1 >> 16], 1u);
    atomicAdd(&g_hist[e][k2 >> 16], 1u);
    atomicAdd(&g_hist[e][k3 >> 16], 1u);
    atomicAdd(&sc[k0 >> 22], 1u);
    atomicAdd(&sc[k1 >> 22], 1u);
    atomicAdd(&sc[k2 >> 22], 1u);
    atomicAdd(&sc[k3 >> 22], 1u);
    __syncthreads();
    #pragma unroll
    for (int j = 0; j < 4; j++) {                       // flush nonzero coarse bins
        unsigned v = sc[t + j * 256];
        if (v) atomicAdd(&g_coarse[e][t + j * 256], v);
    }
}

// Rank-select using precomputed coarse sums: 1 coalesced coarse load + suffix
// scan + 1 warp-load of the winning 64-bin chunk + cheap serial walk.
// phase 0: g_coarse/g_hist  -> (binhi, remaining rank)
// phase 1: g_coarse2/g_hist2 -> exact kth key
__global__ void k_scan(int phase) {
    int e = blockIdx.x;
    int t = threadIdx.x;
    int lane = t & 31, w = t >> 5;
    const unsigned* co = (phase == 0) ? &g_coarse[e][0] : &g_coarse2[e][0];
    const unsigned* h  = (phase == 0) ? &g_hist[e][0]   : &g_hist2[e][0];
    __shared__ unsigned ss[NCRS];
    __shared__ unsigned sel[2];       // [chunk id, cum above chunk]
    __shared__ unsigned bins64[64];

    ss[t] = co[t];
    __syncthreads();
    // inclusive suffix sum: ss[t] = sum_{j>=t}
    for (int off = 1; off < NCRS; off <<= 1) {
        unsigned v = (t + off < NCRS) ? ss[t + off] : 0u;
        __syncthreads();
        ss[t] += v;
        __syncthreads();
    }

    unsigned target = (phase == 0) ? (unsigned)KSEL : g_rank[e];
    unsigned above = (t < NCRS - 1) ? ss[t + 1] : 0u;
    if (ss[t] >= target && above < target) { sel[0] = (unsigned)t; sel[1] = above; }
    __syncthreads();

    unsigned cstar = sel[0], cum0 = sel[1];
    if (w == 0) {                               // coalesced fetch of winning chunk
        bins64[lane]      = h[cstar * 64 + lane];
        bins64[lane + 32] = h[cstar * 64 + 32 + lane];
    }
    __syncthreads();

    if (t == 0) {
        unsigned cum = cum0;
        unsigned bin = cstar * 64;
        for (int j = 63; j >= 0; j--) {         // walk 64 bins in shared (cheap)
            unsigned v = bins64[j];
            if (cum + v >= target) { bin = cstar * 64 + j; break; }
            cum += v;
        }
        if (phase == 0) { g_binhi[e] = bin; g_rank[e] = target - cum; }
        else            { g_kth[e]  = (g_binhi[e] << 16) | bin; }
    }
}

// Lo-16 fine histogram (restricted to the selected hi-bin) + its coarse sums.
// Also re-zeroes g_hist and g_coarse so the next graph replay starts clean.
__global__ void k_hist2() {
    __shared__ unsigned sc[NCRS];
    int e = blockIdx.y;
    unsigned hi = g_binhi[e];
    int t = threadIdx.x;
    int tid = blockIdx.x * 256 + t;
    sc[t] = 0u; sc[t + 256] = 0u; sc[t + 512] = 0u; sc[t + 768] = 0u;
    (&g_hist[0][0])[e * NBIN + tid] = 0u;               // coalesced free zeroing
    if (tid < NCRS) g_coarse[e][tid] = 0u;
    __syncthreads();

    int i = tid * 4;
    float4 m = *(const float4*)(&g_M[e][i]);
    unsigned k0 = fkey(m.x), k1 = fkey(m.y), k2 = fkey(m.z), k3 = fkey(m.w);
    if ((k0 >> 16) == hi) { atomicAdd(&g_hist2[e][k0 & 0xFFFFu], 1u); atomicAdd(&sc[(k0 & 0xFFFFu) >> 6], 1u); }
    if ((k1 >> 16) == hi) { atomicAdd(&g_hist2[e][k1 & 0xFFFFu], 1u); atomicAdd(&sc[(k1 & 0xFFFFu) >> 6], 1u); }
    if ((k2 >> 16) == hi) { atomicAdd(&g_hist2[e][k2 & 0xFFFFu], 1u); atomicAdd(&sc[(k2 & 0xFFFFu) >> 6], 1u); }
    if ((k3 >> 16) == hi) { atomicAdd(&g_hist2[e][k3 & 0xFFFFu], 1u); atomicAdd(&sc[(k3 & 0xFFFFu) >> 6], 1u); }
    __syncthreads();
    #pragma unroll
    for (int j = 0; j < 4; j++) {
        unsigned v = sc[t + j * 256];
        if (v) atomicAdd(&g_coarse2[e][t + j * 256], v);
    }
}

// Flat streaming writer: single L2 read of g_M per element, MUFU sigmoid,
// 3 dense coalesced float4 streams, PLAIN stores (L2 write-back aggregation).
__global__ void k_out(const int* __restrict__ env_idx,
                      float* __restrict__ outA,
                      float* __restrict__ outL,
                      float* __restrict__ outS) {
    int b = blockIdx.y;
    int e = __ldg(&env_idx[b]);
    unsigned kth = g_kth[e];
    size_t i = ((size_t)blockIdx.x * 256 + threadIdx.x) * 4;
    float4 m = *(const float4*)(&g_M[e][i]);
    float4 s;
    s.x = sigm(m.x); s.y = sigm(m.y); s.z = sigm(m.z); s.w = sigm(m.w);
    float4 a;
    a.x = (fkey(m.x) >= kth) ? s.x : 0.0f;
    a.y = (fkey(m.y) >= kth) ? s.y : 0.0f;
    a.z = (fkey(m.z) >= kth) ? s.z : 0.0f;
    a.w = (fkey(m.w) >= kth) ? s.w : 0.0f;
    size_t off = (size_t)b * DD + i;
    *(float4*)(outA + off) = a;
    *(float4*)(outL + off) = m;
    *(float4*)(outS + off) = s;
}

extern "C" void kernel_launch(void* const* d_in, const int* in_sizes, int n_in,
                              void* d_out, int out_size) {
    const float* base   = nullptr;
    const float* deltas = nullptr;
    const int*   env    = nullptr;
    for (int i = 0; i < n_in; i++) {
        if      (in_sizes[i] == DD)        base   = (const float*)d_in[i];
        else if (in_sizes[i] == NENV * DD) deltas = (const float*)d_in[i];
        else if (in_sizes[i] == NB)        env    = (const int*)d_in[i];
        // z_s (131072 elems) unused by the reference outputs
    }

    dim3 gb(DD / 1024, NENV);               // (256, 4): 1 float4/thread
    k_build<<<gb, 256>>>(base, deltas);
    k_scan<<<NENV, NCRS>>>(0);
    k_hist2<<<gb, 256>>>();
    k_scan<<<NENV, NCRS>>>(1);

    float* outA = (float*)d_out;            // tuple order: (A, A_logits, A_soft)
    float* outL = outA + (size_t)NB * DD;
    float* outS = outL + (size_t)NB * DD;
    dim3 go(DD / 1024, NB);                 // (256, 128): 1 float4/thread
    k_out<<<go, 256>>>(env, outA, outL, outS);
}

// round 10
// speedup vs baseline: 2.2894x; 1.0011x over previous
#include <cuda_runtime.h>

#define DD     262144     // 512*512
#define NB     128        // batch
#define NENV   4
#define KSEL   26214      // floor(0.1 * 512 * 512)
#define NBIN   65536
#define NCRS   1024       // coarse bins = fkey >> 22

// Scratch (allocation-free: __device__ globals, zero-initialized at module load)
__device__ unsigned g_hist[NENV][NBIN];    // fine pass 1 (hi 16 bits)
__device__ unsigned g_hist2[NENV][NBIN];   // fine pass 2 (lo 16 bits)
__device__ unsigned g_coarse[NENV][NCRS];  // chunk sums of g_hist  (fkey>>22)
__device__ unsigned g_coarse2[NENV][NCRS]; // chunk sums of g_hist2 (lo>>6)
__device__ unsigned g_binhi[NENV];
__device__ unsigned g_rank[NENV];
__device__ unsigned g_kth[NENV];           // exact key of k-th largest per env

// Monotone mapping: float total order -> unsigned total order
__device__ __forceinline__ unsigned fkey(float f) {
    unsigned u = __float_as_uint(f);
    return (u & 0x80000000u) ? ~u : (u | 0x80000000u);
}
__device__ __forceinline__ float sigm(float x) {
    return __fdividef(1.0f, 1.0f + __expf(-x));   // MUFU EX2 + fast RCP
}
__device__ __forceinline__ float4 madd(float4 a, float4 b) {
    float4 m; m.x = a.x + b.x; m.y = a.y + b.y; m.z = a.z + b.z; m.w = a.w + b.w;
    return m;
}

// Hi-16 fine histogram + coarse chunk sums (smem-agg). No g_M store.
// Also zeroes g_hist2/g_coarse2 for this call's pass 2.
// Requires g_hist/g_coarse == 0 on entry (load-time zero; re-zeroed by k_hist2).
__global__ void k_build(const float* __restrict__ base, const float* __restrict__ deltas) {
    __shared__ unsigned sc[NCRS];
    int e = blockIdx.y;
    int t = threadIdx.x;                                // 0..255
    int tid = blockIdx.x * 256 + t;                     // 0..65535 per env slice
    sc[t] = 0u; sc[t + 256] = 0u; sc[t + 512] = 0u; sc[t + 768] = 0u;
    (&g_hist2[0][0])[e * NBIN + tid] = 0u;              // coalesced free zeroing
    if (tid < NCRS) g_coarse2[e][tid] = 0u;
    __syncthreads();

    int i = tid * 4;
    float4 m = madd(*(const float4*)(base + i),
                    *(const float4*)(deltas + (size_t)e * DD + i));
    unsigned k0 = fkey(m.x), k1 = fkey(m.y), k2 = fkey(m.z), k3 = fkey(m.w);
    atomicAdd(&g_hist[e][k0 >> 16], 1u);
    atomicAdd(&g_hist[e][k1 >> 16], 1u);
    atomicAdd(&g_hist[e][k2 >> 16], 1u);
    atomicAdd(&g_hist[e][k3 >> 16], 1u);
    atomicAdd(&sc[k0 >> 22], 1u);
    atomicAdd(&sc[k1 >> 22], 1u);
    atomicAdd(&sc[k2 >> 22], 1u);
    atomicAdd(&sc[k3 >> 22], 1u);
    __syncthreads();
    #pragma unroll
    for (int j = 0; j < 4; j++) {                       // flush nonzero coarse bins
        unsigned v = sc[t + j * 256];
        if (v) atomicAdd(&g_coarse[e][t + j * 256], v);
    }
}

// Rank-select using precomputed coarse sums.
// phase 0: g_coarse/g_hist   -> (binhi, remaining rank)
// phase 1: g_coarse2/g_hist2 -> exact kth key
__global__ void k_scan(int phase) {
    int e = blockIdx.x;
    int t = threadIdx.x;
    int lane = t & 31, w = t >> 5;
    const unsigned* co = (phase == 0) ? &g_coarse[e][0] : &g_coarse2[e][0];
    const unsigned* h  = (phase == 0) ? &g_hist[e][0]   : &g_hist2[e][0];
    __shared__ unsigned ss[NCRS];
    __shared__ unsigned sel[2];       // [chunk id, cum above chunk]
    __shared__ unsigned bins64[64];

    ss[t] = co[t];
    __syncthreads();
    for (int off = 1; off < NCRS; off <<= 1) {          // inclusive suffix sum
        unsigned v = (t + off < NCRS) ? ss[t + off] : 0u;
        __syncthreads();
        ss[t] += v;
        __syncthreads();
    }

    unsigned target = (phase == 0) ? (unsigned)KSEL : g_rank[e];
    unsigned above = (t < NCRS - 1) ? ss[t + 1] : 0u;
    if (ss[t] >= target && above < target) { sel[0] = (unsigned)t; sel[1] = above; }
    __syncthreads();

    unsigned cstar = sel[0], cum0 = sel[1];
    if (w == 0) {                                       // coalesced winning chunk
        bins64[lane]      = h[cstar * 64 + lane];
        bins64[lane + 32] = h[cstar * 64 + 32 + lane];
    }
    __syncthreads();

    if (t == 0) {
        unsigned cum = cum0;
        unsigned bin = cstar * 64;
        for (int j = 63; j >= 0; j--) {
            unsigned v = bins64[j];
            if (cum + v >= target) { bin = cstar * 64 + j; break; }
            cum += v;
        }
        if (phase == 0) { g_binhi[e] = bin; g_rank[e] = target - cum; }
        else            { g_kth[e]  = (g_binhi[e] << 16) | bin; }
    }
}

// Lo-16 fine histogram (restricted to selected hi-bin) + coarse sums.
// Recomputes m from base+deltas (L2-hot). Re-zeroes g_hist/g_coarse for replay.
__global__ void k_hist2(const float* __restrict__ base, const float* __restrict__ deltas) {
    __shared__ unsigned sc[NCRS];
    int e = blockIdx.y;
    unsigned hi = g_binhi[e];
    int t = threadIdx.x;
    int tid = blockIdx.x * 256 + t;
    sc[t] = 0u; sc[t + 256] = 0u; sc[t + 512] = 0u; sc[t + 768] = 0u;
    (&g_hist[0][0])[e * NBIN + tid] = 0u;               // coalesced free zeroing
    if (tid < NCRS) g_coarse[e][tid] = 0u;
    __syncthreads();

    int i = tid * 4;
    float4 m = madd(*(const float4*)(base + i),
                    *(const float4*)(deltas + (size_t)e * DD + i));
    unsigned k0 = fkey(m.x), k1 = fkey(m.y), k2 = fkey(m.z), k3 = fkey(m.w);
    if ((k0 >> 16) == hi) { atomicAdd(&g_hist2[e][k0 & 0xFFFFu], 1u); atomicAdd(&sc[(k0 & 0xFFFFu) >> 6], 1u); }
    if ((k1 >> 16) == hi) { atomicAdd(&g_hist2[e][k1 & 0xFFFFu], 1u); atomicAdd(&sc[(k1 & 0xFFFFu) >> 6], 1u); }
    if ((k2 >> 16) == hi) { atomicAdd(&g_hist2[e][k2 & 0xFFFFu], 1u); atomicAdd(&sc[(k2 & 0xFFFFu) >> 6], 1u); }
    if ((k3 >> 16) == hi) { atomicAdd(&g_hist2[e][k3 & 0xFFFFu], 1u); atomicAdd(&sc[(k3 & 0xFFFFu) >> 6], 1u); }
    __syncthreads();
    #pragma unroll
    for (int j = 0; j < 4; j++) {
        unsigned v = sc[t + j * 256];
        if (v) atomicAdd(&g_coarse2[e][t + j * 256], v);
    }
}

// A_logits + A_soft writer: depends on NOTHING (recomputes m). Runs on a
// side stream concurrent with the whole selection chain. 268 MB of stores.
__global__ void k_outLS(const int* __restrict__ env_idx,
                        float* __restrict__ outL, float* __restrict__ outS,
                        const float* __restrict__ base, const float* __restrict__ deltas) {
    int b = blockIdx.y;
    int e = __ldg(&env_idx[b]);
    size_t i = ((size_t)blockIdx.x * 256 + threadIdx.x) * 4;
    float4 m = madd(*(const float4*)(base + i),
                    *(const float4*)(deltas + (size_t)e * DD + i));
    float4 s;
    s.x = sigm(m.x); s.y = sigm(m.y); s.z = sigm(m.z); s.w = sigm(m.w);
    size_t off = (size_t)b * DD + i;
    *(float4*)(outL + off) = m;
    *(float4*)(outS + off) = s;
}

// A writer: needs only g_kth. 134 MB of stores.
__global__ void k_outA(const int* __restrict__ env_idx,
                       float* __restrict__ outA,
                       const float* __restrict__ base, const float* __restrict__ deltas) {
    int b = blockIdx.y;
    int e = __ldg(&env_idx[b]);
    unsigned kth = g_kth[e];
    size_t i = ((size_t)blockIdx.x * 256 + threadIdx.x) * 4;
    float4 m = madd(*(const float4*)(base + i),
                    *(const float4*)(deltas + (size_t)e * DD + i));
    float4 a;
    a.x = (fkey(m.x) >= kth) ? sigm(m.x) : 0.0f;
    a.y = (fkey(m.y) >= kth) ? sigm(m.y) : 0.0f;
    a.z = (fkey(m.z) >= kth) ? sigm(m.z) : 0.0f;
    a.w = (fkey(m.w) >= kth) ? sigm(m.w) : 0.0f;
    *(float4*)(outA + (size_t)b * DD + i) = a;
}

extern "C" void kernel_launch(void* const* d_in, const int* in_sizes, int n_in,
                              void* d_out, int out_size) {
    // Side stream + events, created once on the (uncaptured) correctness call,
    // reused during capture via the standard fork-join pattern. No device allocs.
    static cudaStream_t s1 = nullptr;
    static cudaEvent_t evFork = nullptr, evJoin = nullptr;
    if (s1 == nullptr) {
        cudaStreamCreateWithFlags(&s1, cudaStreamNonBlocking);
        cudaEventCreateWithFlags(&evFork, cudaEventDisableTiming);
        cudaEventCreateWithFlags(&evJoin, cudaEventDisableTiming);
    }

    const float* base   = nullptr;
    const float* deltas = nullptr;
    const int*   env    = nullptr;
    for (int i = 0; i < n_in; i++) {
        if      (in_sizes[i] == DD)        base   = (const float*)d_in[i];
        else if (in_sizes[i] == NENV * DD) deltas = (const float*)d_in[i];
        else if (in_sizes[i] == NB)        env    = (const int*)d_in[i];
        // z_s (131072 elems) unused by the reference outputs
    }

    float* outA = (float*)d_out;            // tuple order: (A, A_logits, A_soft)
    float* outL = outA + (size_t)NB * DD;
    float* outS = outL + (size_t)NB * DD;

    // Fork: L/S stores run on s1, fully independent of the selection chain.
    cudaEventRecord(evFork, 0);
    cudaStreamWaitEvent(s1, evFork, 0);
    dim3 go(DD / 1024, NB);                 // (256, 128): 1 float4/thread
    k_outLS<<<go, 256, 0, s1>>>(env, outL, outS, base, deltas);

    // Selection chain on the main stream, hidden under k_outLS's stores.
    dim3 gb(DD / 1024, NENV);               // (256, 4)
    k_build<<<gb, 256>>>(base, deltas);
    k_scan<<<NENV, NCRS>>>(0);
    k_hist2<<<gb, 256>>>(base, deltas);
    k_scan<<<NENV, NCRS>>>(1);
    k_outA<<<go, 256>>>(env, outA, base, deltas);

    // Join: main stream completion implies s1 completion.
    cudaEventRecord(evJoin, s1);
    cudaStreamWaitEvent(0, evJoin, 0);
}